// round 9
// baseline (speedup 1.0000x reference)
#include <cuda_runtime.h>
#include <cuda_bf16.h>
#include <math.h>
#include <stdint.h>

#define B  4
#define C  64
#define CR 32
#define HW 65536

// ---------------- scratch (device globals) ----------------------------------
__device__ float d_ps[512][4];                // stats partial sums
__device__ float d_pm[512][4];                // stats partial maxes
__device__ __nv_bfloat16 d_fb[2][B][C][HW];   // bf16 copy of f (written by stats)
__device__ __nv_bfloat16 d_Sb[2][B][C*C];     // softmaxed S, bf16
__device__ float d_pooled[2][B][2][HW];
__device__ float d_t2[2][B][HW];
__device__ float d_g [2][B][HW];
__device__ float d_cmax[8][32];
__device__ float d_csum[8][32];

// ---------------- PTX helpers ------------------------------------------------
__device__ __forceinline__ uint32_t pack_bf16(float lo, float hi) {
    uint32_t d;
    asm("cvt.rn.bf16x2.f32 %0, %1, %2;" : "=r"(d) : "f"(hi), "f"(lo));
    return d;
}
__device__ __forceinline__ void ldsm_x4(uint32_t r[4], uint32_t addr) {
    asm volatile("ldmatrix.sync.aligned.m8n8.x4.shared.b16 {%0,%1,%2,%3}, [%4];"
                 : "=r"(r[0]), "=r"(r[1]), "=r"(r[2]), "=r"(r[3]) : "r"(addr));
}
__device__ __forceinline__ void ldsm_x4_trans(uint32_t r[4], uint32_t addr) {
    asm volatile("ldmatrix.sync.aligned.m8n8.x4.trans.shared.b16 {%0,%1,%2,%3}, [%4];"
                 : "=r"(r[0]), "=r"(r[1]), "=r"(r[2]), "=r"(r[3]) : "r"(addr));
}
__device__ __forceinline__ void mma_bf16(float d[4], const uint32_t a[4],
                                         uint32_t b0, uint32_t b1) {
    asm volatile(
        "mma.sync.aligned.m16n8k16.row.col.f32.bf16.bf16.f32 "
        "{%0,%1,%2,%3}, {%4,%5,%6,%7}, {%8,%9}, {%0,%1,%2,%3};"
        : "+f"(d[0]), "+f"(d[1]), "+f"(d[2]), "+f"(d[3])
        : "r"(a[0]), "r"(a[1]), "r"(a[2]), "r"(a[3]), "r"(b0), "r"(b1));
}
__device__ __forceinline__ void cp_async16(uint32_t dst, const void* src) {
    asm volatile("cp.async.cg.shared.global [%0], [%1], 16;"
                 :: "r"(dst), "l"(src));
}
__device__ __forceinline__ void cp_async_commit() {
    asm volatile("cp.async.commit_group;");
}
template <int N>
__device__ __forceinline__ void cp_async_wait() {
    asm volatile("cp.async.wait_group %0;" :: "n"(N) : "memory");
}

// ---------------- kernel 1: stats partials + bf16 conversion ----------------
__global__ void stats_kernel(const float* __restrict__ f1,
                             const float* __restrict__ f2) {
    int lin   = blockIdx.x;              // 0..2047
    int row   = 511 - (lin >> 2);        // f2 chunks first
    int chunk = lin & 3;
    int z = (row >= 256);
    int idx = row & 255;
    const float* f = (z ? f2 : f1) + (size_t)idx * HW;
    __nv_bfloat16* fbo = &d_fb[z][idx >> 6][idx & 63][chunk * 16384];
    int tid = threadIdx.x;
    const float4* f4 = (const float4*)f + chunk * 4096;

    float s = 0.f, m = -INFINITY;
    #pragma unroll
    for (int k = 0; k < 16; k++) {
        int i = tid + k * 256;
        float4 v = f4[i];
        s += (v.x + v.y) + (v.z + v.w);
        m = fmaxf(m, fmaxf(fmaxf(v.x, v.y), fmaxf(v.z, v.w)));
        uint32_t u0 = pack_bf16(v.x, v.y);
        uint32_t u1 = pack_bf16(v.z, v.w);
        *(uint2*)(fbo + i * 4) = make_uint2(u0, u1);
    }
    __shared__ float ss[256], sm[256];
    ss[tid] = s; sm[tid] = m;
    __syncthreads();
    for (int o = 128; o > 0; o >>= 1) {
        if (tid < o) { ss[tid] += ss[tid + o]; sm[tid] = fmaxf(sm[tid], sm[tid + o]); }
        __syncthreads();
    }
    if (tid == 0) { d_ps[row][chunk] = ss[0]; d_pm[row][chunk] = sm[0]; }
}

// ---------------- kernel 2: reduce partials + MLPs + cross softmax -> bf16 --
__global__ void mlp_kernel(
    const float* __restrict__ w_a1,  const float* __restrict__ b_a1,
    const float* __restrict__ w_m1,  const float* __restrict__ b_m1,
    const float* __restrict__ w_a11, const float* __restrict__ b_a11,
    const float* __restrict__ w_m11, const float* __restrict__ b_m11,
    const float* __restrict__ w_a2,  const float* __restrict__ b_a2,
    const float* __restrict__ w_m2,  const float* __restrict__ b_m2,
    const float* __restrict__ w_a22, const float* __restrict__ b_a22,
    const float* __restrict__ w_m22, const float* __restrict__ b_m22)
{
    __shared__ float s_stat[4][B][C];
    __shared__ float s_hid [4][B][CR];
    __shared__ float s_a   [2][B][C];
    int tid = threadIdx.x;

    {
        int b = tid >> 6, c = tid & 63;
        float s0 = d_ps[tid][0] + d_ps[tid][1] + d_ps[tid][2] + d_ps[tid][3];
        float m0 = fmaxf(fmaxf(d_pm[tid][0], d_pm[tid][1]),
                         fmaxf(d_pm[tid][2], d_pm[tid][3]));
        int r1 = tid + 256;
        float s1 = d_ps[r1][0] + d_ps[r1][1] + d_ps[r1][2] + d_ps[r1][3];
        float m1 = fmaxf(fmaxf(d_pm[r1][0], d_pm[r1][1]),
                         fmaxf(d_pm[r1][2], d_pm[r1][3]));
        s_stat[0][b][c] = s0 * (1.f / HW);
        s_stat[1][b][c] = m0;
        s_stat[2][b][c] = s1 * (1.f / HW);
        s_stat[3][b][c] = m1;
    }
    __syncthreads();

    const float* Wp[4] = {w_a1, w_m1, w_a2, w_m2};
    const float* Bp[4] = {b_a1, b_m1, b_a2, b_m2};
    for (int e = tid; e < 4 * B * CR; e += 256) {
        int p = e >> 7, b = (e >> 5) & 3, k = e & 31;
        const float* wr = Wp[p] + k * C;
        float acc = Bp[p][k];
        #pragma unroll 8
        for (int c2 = 0; c2 < C; c2++) acc += s_stat[p][b][c2] * wr[c2];
        s_hid[p][b][k] = fmaxf(acc, 0.f);
    }
    __syncthreads();

    {
        int b = tid >> 6, i = tid & 63;
        float a1 = b_a11[i] + b_m11[i];
        float a2 = b_a22[i] + b_m22[i];
        #pragma unroll 8
        for (int k = 0; k < CR; k++) {
            a1 += s_hid[0][b][k] * w_a11[i * CR + k] + s_hid[1][b][k] * w_m11[i * CR + k];
            a2 += s_hid[2][b][k] * w_a22[i * CR + k] + s_hid[3][b][k] * w_m22[i * CR + k];
        }
        s_a[0][b][i] = a1;
        s_a[1][b][i] = a2;
    }
    __syncthreads();

    {   // softmax rows -> bf16 directly
        int b = tid >> 6, i = tid & 63;
        for (int zz = 0; zz < 2; zz++) {
            float x = s_a[zz][b][i];
            const float* other = s_a[1 - zz][b];
            float m = -INFINITY;
            #pragma unroll 8
            for (int j = 0; j < C; j++) m = fmaxf(m, x * other[j]);
            float Z = 0.f;
            #pragma unroll 8
            for (int j = 0; j < C; j++) Z += __expf(x * other[j] - m);
            float inv = 1.f / Z;
            __nv_bfloat16* dst = &d_Sb[zz][b][i * C];
            #pragma unroll 8
            for (int j = 0; j < C; j++)
                dst[j] = __float2bfloat16(__expf(x * other[j] - m) * inv);
        }
    }
}

// ---------------- kernel 3: attention pooling, pipelined multi-tile HMMA ----
#define PXT   256
#define TPB   8      // tiles per block -> grid 256 = single wave
#define FROW  264    // bf16 elems; 528B row stride
#define SROW  72     // bf16 elems; 144B row stride
#define ATP_SMEM_BYTES (2 * 64 * FROW * 2 + 64 * SROW * 2)

__global__ void __launch_bounds__(256, 2)
atpool_kernel() {
    extern __shared__ char smraw[];
    __nv_bfloat16* sF0 = (__nv_bfloat16*)smraw;            // [64][FROW]
    __nv_bfloat16* sF1 = sF0 + 64 * FROW;                  // [64][FROW]
    __nv_bfloat16* sS  = sF1 + 64 * FROW;                  // [64][SROW]

    int tid = threadIdx.x, warp = tid >> 5, lane = tid & 31;
    int tg = blockIdx.x, b = blockIdx.y, z = blockIdx.z;
    const __nv_bfloat16* fb = &d_fb[z][b][0][0];
    const __nv_bfloat16* Sg = d_Sb[z][b];

    uint32_t sS_base = (uint32_t)__cvta_generic_to_shared(sS);
    uint32_t sFb[2] = { (uint32_t)__cvta_generic_to_shared(sF0),
                        (uint32_t)__cvta_generic_to_shared(sF1) };

    #pragma unroll
    for (int it = 0; it < 2; it++) {
        int idx = tid + it * 256;
        int row = idx >> 3, col = idx & 7;
        cp_async16(sS_base + row * 144 + col * 16, Sg + row * 64 + col * 8);
    }
    {
        int px0 = tg * TPB * PXT;
        #pragma unroll
        for (int it = 0; it < 8; it++) {
            int idx = tid + it * 256;
            int row = idx >> 5, col = idx & 31;
            cp_async16(sFb[0] + row * 528 + col * 16,
                       fb + (size_t)row * HW + px0 + col * 8);
        }
    }
    cp_async_commit();

    for (int t = 0; t < TPB; t++) {
        int cur = t & 1;
        if (t + 1 < TPB) {
            int px0 = (tg * TPB + t + 1) * PXT;
            uint32_t dstb = sFb[cur ^ 1];
            #pragma unroll
            for (int it = 0; it < 8; it++) {
                int idx = tid + it * 256;
                int row = idx >> 5, col = idx & 31;
                cp_async16(dstb + row * 528 + col * 16,
                           fb + (size_t)row * HW + px0 + col * 8);
            }
            cp_async_commit();
            cp_async_wait<1>();
        } else {
            cp_async_wait<0>();
        }
        __syncthreads();

        int pxw = warp * 32;
        float rm0[4], rm1[4], rs0[4], rs1[4];
        #pragma unroll
        for (int nt = 0; nt < 4; nt++) {
            rm0[nt] = -INFINITY; rm1[nt] = -INFINITY;
            rs0[nt] = 0.f;       rs1[nt] = 0.f;
        }

        #pragma unroll
        for (int mt = 0; mt < 4; mt++) {
            float acc[4][4];
            #pragma unroll
            for (int nt = 0; nt < 4; nt++)
                #pragma unroll
                for (int r = 0; r < 4; r++) acc[nt][r] = 0.f;

            #pragma unroll
            for (int kt = 0; kt < 4; kt++) {
                uint32_t a[4];
                {
                    int row = mt * 16 + (lane & 15);
                    int col = kt * 16 + ((lane & 16) ? 8 : 0);
                    ldsm_x4(a, sS_base + row * 144 + col * 2);
                }
                uint32_t bfr[2][4];
                #pragma unroll
                for (int h = 0; h < 2; h++) {
                    int krow = kt * 16 + (lane & 15);
                    int px   = pxw + h * 16 + ((lane & 16) ? 8 : 0);
                    ldsm_x4_trans(bfr[h], sFb[cur] + krow * 528 + px * 2);
                }
                #pragma unroll
                for (int nt = 0; nt < 4; nt++)
                    mma_bf16(acc[nt], a,
                             bfr[nt >> 1][(nt & 1) * 2 + 0],
                             bfr[nt >> 1][(nt & 1) * 2 + 1]);
            }
            #pragma unroll
            for (int nt = 0; nt < 4; nt++) {
                rm0[nt] = fmaxf(rm0[nt], fmaxf(acc[nt][0], acc[nt][2]));
                rm1[nt] = fmaxf(rm1[nt], fmaxf(acc[nt][1], acc[nt][3]));
                rs0[nt] += acc[nt][0] + acc[nt][2];
                rs1[nt] += acc[nt][1] + acc[nt][3];
            }
        }

        int tpx = (tg * TPB + t) * PXT;
        float* pmax  = &d_pooled[z][b][1][tpx];
        float* pmean = &d_pooled[z][b][0][tpx];
        #pragma unroll
        for (int nt = 0; nt < 4; nt++) {
            float m0 = rm0[nt], m1 = rm1[nt], s0 = rs0[nt], s1 = rs1[nt];
            #pragma unroll
            for (int off = 4; off < 32; off <<= 1) {
                m0 = fmaxf(m0, __shfl_xor_sync(0xffffffffu, m0, off));
                m1 = fmaxf(m1, __shfl_xor_sync(0xffffffffu, m1, off));
                s0 += __shfl_xor_sync(0xffffffffu, s0, off);
                s1 += __shfl_xor_sync(0xffffffffu, s1, off);
            }
            if (lane < 4) {
                int px = pxw + nt * 8 + lane * 2;
                pmax[px]      = m0;
                pmax[px + 1]  = m1;
                pmean[px]     = s0 * (1.f / 64.f);
                pmean[px + 1] = s1 * (1.f / 64.f);
            }
        }
        __syncthreads();
    }
}

// ---------------- kernel 4: fused conv1+conv2 + softmax partials ------------
// 512 threads, 128x16 output tile, halo 2; grid (2,16,8).
__global__ void __launch_bounds__(512)
convf_kernel(const float* __restrict__ cw1, const float* __restrict__ cb1,
             const float* __restrict__ cw2, const float* __restrict__ cb2) {
    __shared__ float in0[20][132];
    __shared__ float in1[20][132];
    __shared__ float t1s[18][130];
    __shared__ float rbuf[512];

    int tid = threadIdx.x;
    int ox = blockIdx.x * 128;
    int oy = blockIdx.y * 16;
    int zb = blockIdx.z; int z = zb >> 2, b = zb & 3;
    const float* p0 = d_pooled[z][b][0];
    const float* p1 = d_pooled[z][b][1];

    float w1r[18], w2r[9];
    #pragma unroll
    for (int i = 0; i < 18; i++) w1r[i] = cw1[i];
    #pragma unroll
    for (int i = 0; i < 9;  i++) w2r[i] = cw2[i];
    float bias1 = cb1[0], bias2 = cb2[0];

    for (int idx = tid; idx < 20 * 132; idx += 512) {
        int ly = idx / 132, lx = idx % 132;
        int gy = oy - 2 + ly, gx = ox - 2 + lx;
        bool ok = (gy >= 0) & (gy < 256) & (gx >= 0) & (gx < 256);
        int q = gy * 256 + gx;
        in0[ly][lx] = ok ? p0[q] : 0.f;
        in1[ly][lx] = ok ? p1[q] : 0.f;
    }
    __syncthreads();

    for (int idx = tid; idx < 18 * 130; idx += 512) {
        int ty = idx / 130, tx = idx % 130;
        int gy = oy - 1 + ty, gx = ox - 1 + tx;
        float v = 0.f;
        if ((gy >= 0) & (gy < 256) & (gx >= 0) & (gx < 256)) {
            float acc = bias1;
            #pragma unroll
            for (int dy = 0; dy < 3; dy++)
                #pragma unroll
                for (int dx = 0; dx < 3; dx++) {
                    acc += w1r[dy * 3 + dx]     * in0[ty + dy][tx + dx];
                    acc += w1r[9 + dy * 3 + dx] * in1[ty + dy][tx + dx];
                }
            v = fmaxf(acc, 0.f);
        }
        t1s[ty][tx] = v;
    }
    __syncthreads();

    float vals[4];
    #pragma unroll
    for (int r = 0; r < 4; r++) {
        int idx = tid + r * 512;
        int y = idx >> 7, x = idx & 127;
        float acc = bias2;
        #pragma unroll
        for (int dy = 0; dy < 3; dy++)
            #pragma unroll
            for (int dx = 0; dx < 3; dx++)
                acc += w2r[dy * 3 + dx] * t1s[y + dy][x + dx];
        vals[r] = acc;
        d_t2[z][b][(oy + y) * 256 + (ox + x)] = acc;
    }

    float lm = fmaxf(fmaxf(vals[0], vals[1]), fmaxf(vals[2], vals[3]));
    rbuf[tid] = lm;
    __syncthreads();
    for (int o = 256; o > 0; o >>= 1) {
        if (tid < o) rbuf[tid] = fmaxf(rbuf[tid], rbuf[tid + o]);
        __syncthreads();
    }
    float Mblk = rbuf[0];
    __syncthreads();
    float ls = __expf(vals[0] - Mblk) + __expf(vals[1] - Mblk)
             + __expf(vals[2] - Mblk) + __expf(vals[3] - Mblk);
    rbuf[tid] = ls;
    __syncthreads();
    for (int o = 256; o > 0; o >>= 1) {
        if (tid < o) rbuf[tid] += rbuf[tid + o];
        __syncthreads();
    }
    if (tid == 0) {
        int blk = blockIdx.y * 2 + blockIdx.x;   // 0..31
        d_cmax[zb][blk] = Mblk;
        d_csum[zb][blk] = rbuf[0];
    }
}

// ---------------- kernel 5: gate = softmax(t2) over HW ----------------------
__global__ void gate_kernel() {
    __shared__ float sM, sS2;
    int tid = threadIdx.x;
    int zb = blockIdx.y; int z = zb >> 2, b = zb & 3;

    if (tid < 32) {
        float m0 = d_cmax[zb][tid];
        float mm = m0;
        #pragma unroll
        for (int off = 16; off > 0; off >>= 1)
            mm = fmaxf(mm, __shfl_xor_sync(0xffffffffu, mm, off));
        float s = d_csum[zb][tid] * __expf(m0 - mm);
        #pragma unroll
        for (int off = 16; off > 0; off >>= 1)
            s += __shfl_xor_sync(0xffffffffu, s, off);
        if (tid == 0) { sM = mm; sS2 = s; }
    }
    __syncthreads();
    float M = sM, rinv = 1.f / sS2;

    int i4 = blockIdx.x * 256 + tid;
    float4 yv = *(const float4*)(&d_t2[z][b][i4 * 4]);
    float4 g;
    g.x = __expf(yv.x - M) * rinv;
    g.y = __expf(yv.y - M) * rinv;
    g.z = __expf(yv.z - M) * rinv;
    g.w = __expf(yv.w - M) * rinv;
    *(float4*)(&d_g[z][b][i4 * 4]) = g;
}

// ---------------- kernel 6: o = f*(1+g), 4 float4 per thread ----------------
__global__ void out_kernel(const float* __restrict__ f1,
                           const float* __restrict__ f2,
                           float* __restrict__ out) {
    unsigned idx = blockIdx.x * 256u + threadIdx.x;   // 16-px group index
    unsigned q   = idx & 4095u;
    unsigned c   = (idx >> 12) & 63u;
    unsigned b   = (idx >> 18) & 3u;
    unsigned z   = 1u - (idx >> 20);                  // f2 first
    const float* f = z ? f2 : f1;

    const float4* gp = (const float4*)&d_g[z][b][q * 16];
    size_t base = ((size_t)(b * 64u + c)) * HW + q * 16u;
    const float4* fp = (const float4*)(f + base);
    float4* op = (float4*)(out + (size_t)z * ((size_t)B * C * HW) + base);

    float4 g0 = gp[0], g1 = gp[1], g2 = gp[2], g3 = gp[3];
    float4 v0 = fp[0], v1 = fp[1], v2 = fp[2], v3 = fp[3];
    float4 o0, o1, o2, o3;
    o0.x = fmaf(v0.x, g0.x, v0.x); o0.y = fmaf(v0.y, g0.y, v0.y);
    o0.z = fmaf(v0.z, g0.z, v0.z); o0.w = fmaf(v0.w, g0.w, v0.w);
    o1.x = fmaf(v1.x, g1.x, v1.x); o1.y = fmaf(v1.y, g1.y, v1.y);
    o1.z = fmaf(v1.z, g1.z, v1.z); o1.w = fmaf(v1.w, g1.w, v1.w);
    o2.x = fmaf(v2.x, g2.x, v2.x); o2.y = fmaf(v2.y, g2.y, v2.y);
    o2.z = fmaf(v2.z, g2.z, v2.z); o2.w = fmaf(v2.w, g2.w, v2.w);
    o3.x = fmaf(v3.x, g3.x, v3.x); o3.y = fmaf(v3.y, g3.y, v3.y);
    o3.z = fmaf(v3.z, g3.z, v3.z); o3.w = fmaf(v3.w, g3.w, v3.w);
    op[0] = o0; op[1] = o1; op[2] = o2; op[3] = o3;
}

// ---------------- launch ------------------------------------------------------
extern "C" void kernel_launch(void* const* d_in, const int* in_sizes, int n_in,
                              void* d_out, int out_size) {
    const float* f1 = (const float*)d_in[0];
    const float* f2 = (const float*)d_in[1];

    cudaFuncSetAttribute(atpool_kernel,
                         cudaFuncAttributeMaxDynamicSharedMemorySize,
                         ATP_SMEM_BYTES);

    stats_kernel<<<2048, 256>>>(f1, f2);

    mlp_kernel<<<1, 256>>>(
        (const float*)d_in[2],  (const float*)d_in[3],
        (const float*)d_in[4],  (const float*)d_in[5],
        (const float*)d_in[6],  (const float*)d_in[7],
        (const float*)d_in[8],  (const float*)d_in[9],
        (const float*)d_in[10], (const float*)d_in[11],
        (const float*)d_in[12], (const float*)d_in[13],
        (const float*)d_in[14], (const float*)d_in[15],
        (const float*)d_in[16], (const float*)d_in[17]);

    atpool_kernel<<<dim3(32, 4, 2), 256, ATP_SMEM_BYTES>>>();

    convf_kernel<<<dim3(2, 16, 8), 512>>>(
        (const float*)d_in[18], (const float*)d_in[19],
        (const float*)d_in[20], (const float*)d_in[21]);

    gate_kernel<<<dim3(64, 8), 256>>>();

    out_kernel<<<8192, 256>>>(f1, f2, (float*)d_out);
}

// round 10
// speedup vs baseline: 1.0843x; 1.0843x over previous
#include <cuda_runtime.h>
#include <cuda_bf16.h>
#include <math.h>
#include <stdint.h>

#define B  4
#define C  64
#define CR 32
#define HW 65536

// ---------------- scratch (device globals) ----------------------------------
__device__ float d_ps[512][4];                // stats partial sums
__device__ float d_pm[512][4];                // stats partial maxes
__device__ __nv_bfloat16 d_fb[2][B][C][HW];   // bf16 copy of f (written by stats)
__device__ __nv_bfloat16 d_Sb[2][B][C*C];     // softmaxed S, bf16
__device__ float d_pooled[2][B][2][HW];
__device__ float d_t2[2][B][HW];
__device__ float d_g [2][B][HW];
__device__ float d_cmax[8][64];
__device__ float d_csum[8][64];

// ---------------- PTX helpers ------------------------------------------------
__device__ __forceinline__ uint32_t pack_bf16(float lo, float hi) {
    uint32_t d;
    asm("cvt.rn.bf16x2.f32 %0, %1, %2;" : "=r"(d) : "f"(hi), "f"(lo));
    return d;
}
__device__ __forceinline__ void ldsm_x4(uint32_t r[4], uint32_t addr) {
    asm volatile("ldmatrix.sync.aligned.m8n8.x4.shared.b16 {%0,%1,%2,%3}, [%4];"
                 : "=r"(r[0]), "=r"(r[1]), "=r"(r[2]), "=r"(r[3]) : "r"(addr));
}
__device__ __forceinline__ void ldsm_x4_trans(uint32_t r[4], uint32_t addr) {
    asm volatile("ldmatrix.sync.aligned.m8n8.x4.trans.shared.b16 {%0,%1,%2,%3}, [%4];"
                 : "=r"(r[0]), "=r"(r[1]), "=r"(r[2]), "=r"(r[3]) : "r"(addr));
}
__device__ __forceinline__ void mma_bf16(float d[4], const uint32_t a[4],
                                         uint32_t b0, uint32_t b1) {
    asm volatile(
        "mma.sync.aligned.m16n8k16.row.col.f32.bf16.bf16.f32 "
        "{%0,%1,%2,%3}, {%4,%5,%6,%7}, {%8,%9}, {%0,%1,%2,%3};"
        : "+f"(d[0]), "+f"(d[1]), "+f"(d[2]), "+f"(d[3])
        : "r"(a[0]), "r"(a[1]), "r"(a[2]), "r"(a[3]), "r"(b0), "r"(b1));
}
__device__ __forceinline__ void cp_async16(uint32_t dst, const void* src) {
    asm volatile("cp.async.cg.shared.global [%0], [%1], 16;"
                 :: "r"(dst), "l"(src));
}
__device__ __forceinline__ void cp_async_commit() {
    asm volatile("cp.async.commit_group;");
}
template <int N>
__device__ __forceinline__ void cp_async_wait() {
    asm volatile("cp.async.wait_group %0;" :: "n"(N) : "memory");
}

// ---------------- kernel 1: stats partials + bf16 conversion ----------------
__global__ void stats_kernel(const float* __restrict__ f1,
                             const float* __restrict__ f2) {
    int lin   = blockIdx.x;              // 0..2047
    int row   = 511 - (lin >> 2);        // f2 chunks first
    int chunk = lin & 3;
    int z = (row >= 256);
    int idx = row & 255;
    const float* f = (z ? f2 : f1) + (size_t)idx * HW;
    __nv_bfloat16* fbo = &d_fb[z][idx >> 6][idx & 63][chunk * 16384];
    int tid = threadIdx.x;
    const float4* f4 = (const float4*)f + chunk * 4096;

    float s = 0.f, m = -INFINITY;
    #pragma unroll
    for (int k = 0; k < 16; k++) {
        int i = tid + k * 256;
        float4 v = f4[i];
        s += (v.x + v.y) + (v.z + v.w);
        m = fmaxf(m, fmaxf(fmaxf(v.x, v.y), fmaxf(v.z, v.w)));
        uint32_t u0 = pack_bf16(v.x, v.y);
        uint32_t u1 = pack_bf16(v.z, v.w);
        *(uint2*)(fbo + i * 4) = make_uint2(u0, u1);
    }
    __shared__ float ss[256], sm[256];
    ss[tid] = s; sm[tid] = m;
    __syncthreads();
    for (int o = 128; o > 0; o >>= 1) {
        if (tid < o) { ss[tid] += ss[tid + o]; sm[tid] = fmaxf(sm[tid], sm[tid + o]); }
        __syncthreads();
    }
    if (tid == 0) { d_ps[row][chunk] = ss[0]; d_pm[row][chunk] = sm[0]; }
}

// ---------------- kernel 2: reduce partials + MLPs + cross softmax -> bf16 --
__global__ void mlp_kernel(
    const float* __restrict__ w_a1,  const float* __restrict__ b_a1,
    const float* __restrict__ w_m1,  const float* __restrict__ b_m1,
    const float* __restrict__ w_a11, const float* __restrict__ b_a11,
    const float* __restrict__ w_m11, const float* __restrict__ b_m11,
    const float* __restrict__ w_a2,  const float* __restrict__ b_a2,
    const float* __restrict__ w_m2,  const float* __restrict__ b_m2,
    const float* __restrict__ w_a22, const float* __restrict__ b_a22,
    const float* __restrict__ w_m22, const float* __restrict__ b_m22)
{
    __shared__ float s_stat[4][B][C];
    __shared__ float s_hid [4][B][CR];
    __shared__ float s_a   [2][B][C];
    int tid = threadIdx.x;

    {
        int b = tid >> 6, c = tid & 63;
        float s0 = d_ps[tid][0] + d_ps[tid][1] + d_ps[tid][2] + d_ps[tid][3];
        float m0 = fmaxf(fmaxf(d_pm[tid][0], d_pm[tid][1]),
                         fmaxf(d_pm[tid][2], d_pm[tid][3]));
        int r1 = tid + 256;
        float s1 = d_ps[r1][0] + d_ps[r1][1] + d_ps[r1][2] + d_ps[r1][3];
        float m1 = fmaxf(fmaxf(d_pm[r1][0], d_pm[r1][1]),
                         fmaxf(d_pm[r1][2], d_pm[r1][3]));
        s_stat[0][b][c] = s0 * (1.f / HW);
        s_stat[1][b][c] = m0;
        s_stat[2][b][c] = s1 * (1.f / HW);
        s_stat[3][b][c] = m1;
    }
    __syncthreads();

    const float* Wp[4] = {w_a1, w_m1, w_a2, w_m2};
    const float* Bp[4] = {b_a1, b_m1, b_a2, b_m2};
    for (int e = tid; e < 4 * B * CR; e += 256) {
        int p = e >> 7, b = (e >> 5) & 3, k = e & 31;
        const float* wr = Wp[p] + k * C;
        float acc = Bp[p][k];
        #pragma unroll 8
        for (int c2 = 0; c2 < C; c2++) acc += s_stat[p][b][c2] * wr[c2];
        s_hid[p][b][k] = fmaxf(acc, 0.f);
    }
    __syncthreads();

    {
        int b = tid >> 6, i = tid & 63;
        float a1 = b_a11[i] + b_m11[i];
        float a2 = b_a22[i] + b_m22[i];
        #pragma unroll 8
        for (int k = 0; k < CR; k++) {
            a1 += s_hid[0][b][k] * w_a11[i * CR + k] + s_hid[1][b][k] * w_m11[i * CR + k];
            a2 += s_hid[2][b][k] * w_a22[i * CR + k] + s_hid[3][b][k] * w_m22[i * CR + k];
        }
        s_a[0][b][i] = a1;
        s_a[1][b][i] = a2;
    }
    __syncthreads();

    {   // softmax rows -> bf16 directly
        int b = tid >> 6, i = tid & 63;
        for (int zz = 0; zz < 2; zz++) {
            float x = s_a[zz][b][i];
            const float* other = s_a[1 - zz][b];
            float m = -INFINITY;
            #pragma unroll 8
            for (int j = 0; j < C; j++) m = fmaxf(m, x * other[j]);
            float Z = 0.f;
            #pragma unroll 8
            for (int j = 0; j < C; j++) Z += __expf(x * other[j] - m);
            float inv = 1.f / Z;
            __nv_bfloat16* dst = &d_Sb[zz][b][i * C];
            #pragma unroll 8
            for (int j = 0; j < C; j++)
                dst[j] = __float2bfloat16(__expf(x * other[j] - m) * inv);
        }
    }
}

// ---------------- kernel 3: attention pooling, pipelined multi-tile HMMA ----
// R8 config: TPB=4, grid (64,4,2) = 512 blocks.
#define PXT   256
#define TPB   4
#define FROW  264    // bf16 elems; 528B row stride
#define SROW  72     // bf16 elems; 144B row stride
#define ATP_SMEM_BYTES (2 * 64 * FROW * 2 + 64 * SROW * 2)

__global__ void __launch_bounds__(256, 2)
atpool_kernel() {
    extern __shared__ char smraw[];
    __nv_bfloat16* sF0 = (__nv_bfloat16*)smraw;            // [64][FROW]
    __nv_bfloat16* sF1 = sF0 + 64 * FROW;                  // [64][FROW]
    __nv_bfloat16* sS  = sF1 + 64 * FROW;                  // [64][SROW]

    int tid = threadIdx.x, warp = tid >> 5, lane = tid & 31;
    int tg = blockIdx.x, b = blockIdx.y, z = blockIdx.z;
    const __nv_bfloat16* fb = &d_fb[z][b][0][0];
    const __nv_bfloat16* Sg = d_Sb[z][b];

    uint32_t sS_base = (uint32_t)__cvta_generic_to_shared(sS);
    uint32_t sFb[2] = { (uint32_t)__cvta_generic_to_shared(sF0),
                        (uint32_t)__cvta_generic_to_shared(sF1) };

    #pragma unroll
    for (int it = 0; it < 2; it++) {
        int idx = tid + it * 256;
        int row = idx >> 3, col = idx & 7;
        cp_async16(sS_base + row * 144 + col * 16, Sg + row * 64 + col * 8);
    }
    {
        int px0 = tg * TPB * PXT;
        #pragma unroll
        for (int it = 0; it < 8; it++) {
            int idx = tid + it * 256;
            int row = idx >> 5, col = idx & 31;
            cp_async16(sFb[0] + row * 528 + col * 16,
                       fb + (size_t)row * HW + px0 + col * 8);
        }
    }
    cp_async_commit();

    for (int t = 0; t < TPB; t++) {
        int cur = t & 1;
        if (t + 1 < TPB) {
            int px0 = (tg * TPB + t + 1) * PXT;
            uint32_t dstb = sFb[cur ^ 1];
            #pragma unroll
            for (int it = 0; it < 8; it++) {
                int idx = tid + it * 256;
                int row = idx >> 5, col = idx & 31;
                cp_async16(dstb + row * 528 + col * 16,
                           fb + (size_t)row * HW + px0 + col * 8);
            }
            cp_async_commit();
            cp_async_wait<1>();
        } else {
            cp_async_wait<0>();
        }
        __syncthreads();

        int pxw = warp * 32;
        float rm0[4], rm1[4], rs0[4], rs1[4];
        #pragma unroll
        for (int nt = 0; nt < 4; nt++) {
            rm0[nt] = -INFINITY; rm1[nt] = -INFINITY;
            rs0[nt] = 0.f;       rs1[nt] = 0.f;
        }

        #pragma unroll
        for (int mt = 0; mt < 4; mt++) {
            float acc[4][4];
            #pragma unroll
            for (int nt = 0; nt < 4; nt++)
                #pragma unroll
                for (int r = 0; r < 4; r++) acc[nt][r] = 0.f;

            #pragma unroll
            for (int kt = 0; kt < 4; kt++) {
                uint32_t a[4];
                {
                    int row = mt * 16 + (lane & 15);
                    int col = kt * 16 + ((lane & 16) ? 8 : 0);
                    ldsm_x4(a, sS_base + row * 144 + col * 2);
                }
                uint32_t bfr[2][4];
                #pragma unroll
                for (int h = 0; h < 2; h++) {
                    int krow = kt * 16 + (lane & 15);
                    int px   = pxw + h * 16 + ((lane & 16) ? 8 : 0);
                    ldsm_x4_trans(bfr[h], sFb[cur] + krow * 528 + px * 2);
                }
                #pragma unroll
                for (int nt = 0; nt < 4; nt++)
                    mma_bf16(acc[nt], a,
                             bfr[nt >> 1][(nt & 1) * 2 + 0],
                             bfr[nt >> 1][(nt & 1) * 2 + 1]);
            }
            #pragma unroll
            for (int nt = 0; nt < 4; nt++) {
                rm0[nt] = fmaxf(rm0[nt], fmaxf(acc[nt][0], acc[nt][2]));
                rm1[nt] = fmaxf(rm1[nt], fmaxf(acc[nt][1], acc[nt][3]));
                rs0[nt] += acc[nt][0] + acc[nt][2];
                rs1[nt] += acc[nt][1] + acc[nt][3];
            }
        }

        int tpx = (tg * TPB + t) * PXT;
        float* pmax  = &d_pooled[z][b][1][tpx];
        float* pmean = &d_pooled[z][b][0][tpx];
        #pragma unroll
        for (int nt = 0; nt < 4; nt++) {
            float m0 = rm0[nt], m1 = rm1[nt], s0 = rs0[nt], s1 = rs1[nt];
            #pragma unroll
            for (int off = 4; off < 32; off <<= 1) {
                m0 = fmaxf(m0, __shfl_xor_sync(0xffffffffu, m0, off));
                m1 = fmaxf(m1, __shfl_xor_sync(0xffffffffu, m1, off));
                s0 += __shfl_xor_sync(0xffffffffu, s0, off);
                s1 += __shfl_xor_sync(0xffffffffu, s1, off);
            }
            if (lane < 4) {
                int px = pxw + nt * 8 + lane * 2;
                pmax[px]      = m0;
                pmax[px + 1]  = m1;
                pmean[px]     = s0 * (1.f / 64.f);
                pmean[px + 1] = s1 * (1.f / 64.f);
            }
        }
        __syncthreads();
    }
}

// ---------------- kernel 4: fused conv1+conv2 + softmax partials ------------
// R8 config: 256 threads, 64x16 tile, grid (4,16,8).
#define CTX 64
#define CTY 16
__global__ void __launch_bounds__(256)
convf_kernel(const float* __restrict__ cw1, const float* __restrict__ cb1,
             const float* __restrict__ cw2, const float* __restrict__ cb2) {
    __shared__ float in0[20][68];
    __shared__ float in1[20][68];
    __shared__ float t1s[18][66];
    __shared__ float rbuf[256];

    int tid = threadIdx.x;
    int ox = blockIdx.x * CTX;
    int oy = blockIdx.y * CTY;
    int zb = blockIdx.z; int z = zb >> 2, b = zb & 3;
    const float* p0 = d_pooled[z][b][0];
    const float* p1 = d_pooled[z][b][1];

    float w1r[18], w2r[9];
    #pragma unroll
    for (int i = 0; i < 18; i++) w1r[i] = cw1[i];
    #pragma unroll
    for (int i = 0; i < 9;  i++) w2r[i] = cw2[i];
    float bias1 = cb1[0], bias2 = cb2[0];

    for (int idx = tid; idx < 20 * 68; idx += 256) {
        int ly = idx / 68, lx = idx % 68;
        int gy = oy - 2 + ly, gx = ox - 2 + lx;
        bool ok = (gy >= 0) & (gy < 256) & (gx >= 0) & (gx < 256);
        int q = gy * 256 + gx;
        in0[ly][lx] = ok ? p0[q] : 0.f;
        in1[ly][lx] = ok ? p1[q] : 0.f;
    }
    __syncthreads();

    for (int idx = tid; idx < 18 * 66; idx += 256) {
        int ty = idx / 66, tx = idx % 66;
        int gy = oy - 1 + ty, gx = ox - 1 + tx;
        float v = 0.f;
        if ((gy >= 0) & (gy < 256) & (gx >= 0) & (gx < 256)) {
            float acc = bias1;
            #pragma unroll
            for (int dy = 0; dy < 3; dy++)
                #pragma unroll
                for (int dx = 0; dx < 3; dx++) {
                    acc += w1r[dy * 3 + dx]     * in0[ty + dy][tx + dx];
                    acc += w1r[9 + dy * 3 + dx] * in1[ty + dy][tx + dx];
                }
            v = fmaxf(acc, 0.f);
        }
        t1s[ty][tx] = v;
    }
    __syncthreads();

    float vals[4];
    #pragma unroll
    for (int r = 0; r < 4; r++) {
        int idx = tid + r * 256;
        int y = idx >> 6, x = idx & 63;
        float acc = bias2;
        #pragma unroll
        for (int dy = 0; dy < 3; dy++)
            #pragma unroll
            for (int dx = 0; dx < 3; dx++)
                acc += w2r[dy * 3 + dx] * t1s[y + dy][x + dx];
        vals[r] = acc;
        d_t2[z][b][(oy + y) * 256 + (ox + x)] = acc;
    }

    float lm = fmaxf(fmaxf(vals[0], vals[1]), fmaxf(vals[2], vals[3]));
    rbuf[tid] = lm;
    __syncthreads();
    for (int o = 128; o > 0; o >>= 1) {
        if (tid < o) rbuf[tid] = fmaxf(rbuf[tid], rbuf[tid + o]);
        __syncthreads();
    }
    float Mblk = rbuf[0];
    __syncthreads();
    float ls = __expf(vals[0] - Mblk) + __expf(vals[1] - Mblk)
             + __expf(vals[2] - Mblk) + __expf(vals[3] - Mblk);
    rbuf[tid] = ls;
    __syncthreads();
    for (int o = 128; o > 0; o >>= 1) {
        if (tid < o) rbuf[tid] += rbuf[tid + o];
        __syncthreads();
    }
    if (tid == 0) {
        int blk = blockIdx.y * 4 + blockIdx.x;   // 0..63
        d_cmax[zb][blk] = Mblk;
        d_csum[zb][blk] = rbuf[0];
    }
}

// ---------------- kernel 5: gate = softmax(t2) over HW ----------------------
__global__ void gate_kernel() {
    __shared__ float sM, sS2;
    int tid = threadIdx.x;
    int zb = blockIdx.y; int z = zb >> 2, b = zb & 3;

    if (tid < 32) {
        float m0 = d_cmax[zb][tid], m1 = d_cmax[zb][tid + 32];
        float mm = fmaxf(m0, m1);
        #pragma unroll
        for (int off = 16; off > 0; off >>= 1)
            mm = fmaxf(mm, __shfl_xor_sync(0xffffffffu, mm, off));
        float s = d_csum[zb][tid]      * __expf(m0 - mm)
                + d_csum[zb][tid + 32] * __expf(m1 - mm);
        #pragma unroll
        for (int off = 16; off > 0; off >>= 1)
            s += __shfl_xor_sync(0xffffffffu, s, off);
        if (tid == 0) { sM = mm; sS2 = s; }
    }
    __syncthreads();
    float M = sM, rinv = 1.f / sS2;

    int i4 = blockIdx.x * 256 + tid;
    float4 yv = *(const float4*)(&d_t2[z][b][i4 * 4]);
    float4 g;
    g.x = __expf(yv.x - M) * rinv;
    g.y = __expf(yv.y - M) * rinv;
    g.z = __expf(yv.z - M) * rinv;
    g.w = __expf(yv.w - M) * rinv;
    *(float4*)(&d_g[z][b][i4 * 4]) = g;
}

// ---------------- kernel 6: o = f*(1+g), 2 float4 per thread ----------------
__global__ void out_kernel(const float* __restrict__ f1,
                           const float* __restrict__ f2,
                           float* __restrict__ out) {
    unsigned idx  = blockIdx.x * 256u + threadIdx.x;
    unsigned pr   = idx & 8191u;
    unsigned c    = (idx >> 13) & 63u;
    unsigned b    = (idx >> 19) & 3u;
    unsigned z    = 1u - (idx >> 21);
    const float* f = z ? f2 : f1;

    const float4* gp = (const float4*)&d_g[z][b][pr * 8];
    float4 g0 = gp[0], g1 = gp[1];
    size_t base = ((size_t)(b * 64u + c)) * HW + pr * 8u;
    const float4* fp = (const float4*)(f + base);
    float4 v0 = fp[0], v1 = fp[1];
    float4 o0, o1;
    o0.x = fmaf(v0.x, g0.x, v0.x); o0.y = fmaf(v0.y, g0.y, v0.y);
    o0.z = fmaf(v0.z, g0.z, v0.z); o0.w = fmaf(v0.w, g0.w, v0.w);
    o1.x = fmaf(v1.x, g1.x, v1.x); o1.y = fmaf(v1.y, g1.y, v1.y);
    o1.z = fmaf(v1.z, g1.z, v1.z); o1.w = fmaf(v1.w, g1.w, v1.w);
    float4* op = (float4*)(out + (size_t)z * ((size_t)B * C * HW) + base);
    op[0] = o0; op[1] = o1;
}

// ---------------- launch ------------------------------------------------------
extern "C" void kernel_launch(void* const* d_in, const int* in_sizes, int n_in,
                              void* d_out, int out_size) {
    const float* f1 = (const float*)d_in[0];
    const float* f2 = (const float*)d_in[1];

    cudaFuncSetAttribute(atpool_kernel,
                         cudaFuncAttributeMaxDynamicSharedMemorySize,
                         ATP_SMEM_BYTES);

    stats_kernel<<<2048, 256>>>(f1, f2);

    mlp_kernel<<<1, 256>>>(
        (const float*)d_in[2],  (const float*)d_in[3],
        (const float*)d_in[4],  (const float*)d_in[5],
        (const float*)d_in[6],  (const float*)d_in[7],
        (const float*)d_in[8],  (const float*)d_in[9],
        (const float*)d_in[10], (const float*)d_in[11],
        (const float*)d_in[12], (const float*)d_in[13],
        (const float*)d_in[14], (const float*)d_in[15],
        (const float*)d_in[16], (const float*)d_in[17]);

    atpool_kernel<<<dim3(64, 4, 2), 256, ATP_SMEM_BYTES>>>();

    convf_kernel<<<dim3(4, 16, 8), 256>>>(
        (const float*)d_in[18], (const float*)d_in[19],
        (const float*)d_in[20], (const float*)d_in[21]);

    gate_kernel<<<dim3(64, 8), 256>>>();

    out_kernel<<<16384, 256>>>(f1, f2, (float*)d_out);
}

// round 11
// speedup vs baseline: 1.0849x; 1.0005x over previous
#include <cuda_runtime.h>
#include <cuda_bf16.h>
#include <math.h>
#include <stdint.h>

#define B  4
#define C  64
#define CR 32
#define HW 65536

// ---------------- scratch (device globals) ----------------------------------
__device__ float d_ps[512][4];                // stats partial sums
__device__ float d_pm[512][4];                // stats partial maxes
__device__ __nv_bfloat16 d_fb[2][B][C][HW];   // bf16 copy of f (written by stats)
__device__ __nv_bfloat16 d_Sb[2][B][C*C];     // softmaxed S, bf16
__device__ float d_pooled[2][B][2][HW];
__device__ float d_t2[2][B][HW];
__device__ float d_g [2][B][HW];
__device__ float d_cmax[8][64];
__device__ float d_csum[8][64];

// ---------------- PTX helpers ------------------------------------------------
__device__ __forceinline__ uint32_t pack_bf16(float lo, float hi) {
    uint32_t d;
    asm("cvt.rn.bf16x2.f32 %0, %1, %2;" : "=r"(d) : "f"(hi), "f"(lo));
    return d;
}
__device__ __forceinline__ void ldsm_x4(uint32_t r[4], uint32_t addr) {
    asm volatile("ldmatrix.sync.aligned.m8n8.x4.shared.b16 {%0,%1,%2,%3}, [%4];"
                 : "=r"(r[0]), "=r"(r[1]), "=r"(r[2]), "=r"(r[3]) : "r"(addr));
}
__device__ __forceinline__ void ldsm_x4_trans(uint32_t r[4], uint32_t addr) {
    asm volatile("ldmatrix.sync.aligned.m8n8.x4.trans.shared.b16 {%0,%1,%2,%3}, [%4];"
                 : "=r"(r[0]), "=r"(r[1]), "=r"(r[2]), "=r"(r[3]) : "r"(addr));
}
__device__ __forceinline__ void mma_bf16(float d[4], const uint32_t a[4],
                                         uint32_t b0, uint32_t b1) {
    asm volatile(
        "mma.sync.aligned.m16n8k16.row.col.f32.bf16.bf16.f32 "
        "{%0,%1,%2,%3}, {%4,%5,%6,%7}, {%8,%9}, {%0,%1,%2,%3};"
        : "+f"(d[0]), "+f"(d[1]), "+f"(d[2]), "+f"(d[3])
        : "r"(a[0]), "r"(a[1]), "r"(a[2]), "r"(a[3]), "r"(b0), "r"(b1));
}
__device__ __forceinline__ void cp_async16(uint32_t dst, const void* src) {
    asm volatile("cp.async.cg.shared.global [%0], [%1], 16;"
                 :: "r"(dst), "l"(src));
}
__device__ __forceinline__ void cp_async_commit() {
    asm volatile("cp.async.commit_group;");
}
template <int N>
__device__ __forceinline__ void cp_async_wait() {
    asm volatile("cp.async.wait_group %0;" :: "n"(N) : "memory");
}

// ---------------- kernel 1: stats partials + bf16 conversion ----------------
__global__ void stats_kernel(const float* __restrict__ f1,
                             const float* __restrict__ f2) {
    int lin   = blockIdx.x;              // 0..2047
    int row   = 511 - (lin >> 2);        // f2 chunks first
    int chunk = lin & 3;
    int z = (row >= 256);
    int idx = row & 255;
    const float* f = (z ? f2 : f1) + (size_t)idx * HW;
    __nv_bfloat16* fbo = &d_fb[z][idx >> 6][idx & 63][chunk * 16384];
    int tid = threadIdx.x;
    const float4* f4 = (const float4*)f + chunk * 4096;

    float s = 0.f, m = -INFINITY;
    #pragma unroll
    for (int k = 0; k < 16; k++) {
        int i = tid + k * 256;
        float4 v = f4[i];
        s += (v.x + v.y) + (v.z + v.w);
        m = fmaxf(m, fmaxf(fmaxf(v.x, v.y), fmaxf(v.z, v.w)));
        uint32_t u0 = pack_bf16(v.x, v.y);
        uint32_t u1 = pack_bf16(v.z, v.w);
        *(uint2*)(fbo + i * 4) = make_uint2(u0, u1);
    }
    __shared__ float ss[256], sm[256];
    ss[tid] = s; sm[tid] = m;
    __syncthreads();
    for (int o = 128; o > 0; o >>= 1) {
        if (tid < o) { ss[tid] += ss[tid + o]; sm[tid] = fmaxf(sm[tid], sm[tid + o]); }
        __syncthreads();
    }
    if (tid == 0) { d_ps[row][chunk] = ss[0]; d_pm[row][chunk] = sm[0]; }
}

// ---------------- kernel 2: reduce partials + MLPs + cross softmax -> bf16 --
__global__ void mlp_kernel(
    const float* __restrict__ w_a1,  const float* __restrict__ b_a1,
    const float* __restrict__ w_m1,  const float* __restrict__ b_m1,
    const float* __restrict__ w_a11, const float* __restrict__ b_a11,
    const float* __restrict__ w_m11, const float* __restrict__ b_m11,
    const float* __restrict__ w_a2,  const float* __restrict__ b_a2,
    const float* __restrict__ w_m2,  const float* __restrict__ b_m2,
    const float* __restrict__ w_a22, const float* __restrict__ b_a22,
    const float* __restrict__ w_m22, const float* __restrict__ b_m22)
{
    __shared__ float s_stat[4][B][C];
    __shared__ float s_hid [4][B][CR];
    __shared__ float s_a   [2][B][C];
    int tid = threadIdx.x;

    {
        int b = tid >> 6, c = tid & 63;
        float s0 = d_ps[tid][0] + d_ps[tid][1] + d_ps[tid][2] + d_ps[tid][3];
        float m0 = fmaxf(fmaxf(d_pm[tid][0], d_pm[tid][1]),
                         fmaxf(d_pm[tid][2], d_pm[tid][3]));
        int r1 = tid + 256;
        float s1 = d_ps[r1][0] + d_ps[r1][1] + d_ps[r1][2] + d_ps[r1][3];
        float m1 = fmaxf(fmaxf(d_pm[r1][0], d_pm[r1][1]),
                         fmaxf(d_pm[r1][2], d_pm[r1][3]));
        s_stat[0][b][c] = s0 * (1.f / HW);
        s_stat[1][b][c] = m0;
        s_stat[2][b][c] = s1 * (1.f / HW);
        s_stat[3][b][c] = m1;
    }
    __syncthreads();

    const float* Wp[4] = {w_a1, w_m1, w_a2, w_m2};
    const float* Bp[4] = {b_a1, b_m1, b_a2, b_m2};
    for (int e = tid; e < 4 * B * CR; e += 256) {
        int p = e >> 7, b = (e >> 5) & 3, k = e & 31;
        const float* wr = Wp[p] + k * C;
        float acc = Bp[p][k];
        #pragma unroll 8
        for (int c2 = 0; c2 < C; c2++) acc += s_stat[p][b][c2] * wr[c2];
        s_hid[p][b][k] = fmaxf(acc, 0.f);
    }
    __syncthreads();

    {
        int b = tid >> 6, i = tid & 63;
        float a1 = b_a11[i] + b_m11[i];
        float a2 = b_a22[i] + b_m22[i];
        #pragma unroll 8
        for (int k = 0; k < CR; k++) {
            a1 += s_hid[0][b][k] * w_a11[i * CR + k] + s_hid[1][b][k] * w_m11[i * CR + k];
            a2 += s_hid[2][b][k] * w_a22[i * CR + k] + s_hid[3][b][k] * w_m22[i * CR + k];
        }
        s_a[0][b][i] = a1;
        s_a[1][b][i] = a2;
    }
    __syncthreads();

    {   // softmax rows -> bf16 directly
        int b = tid >> 6, i = tid & 63;
        for (int zz = 0; zz < 2; zz++) {
            float x = s_a[zz][b][i];
            const float* other = s_a[1 - zz][b];
            float m = -INFINITY;
            #pragma unroll 8
            for (int j = 0; j < C; j++) m = fmaxf(m, x * other[j]);
            float Z = 0.f;
            #pragma unroll 8
            for (int j = 0; j < C; j++) Z += __expf(x * other[j] - m);
            float inv = 1.f / Z;
            __nv_bfloat16* dst = &d_Sb[zz][b][i * C];
            #pragma unroll 8
            for (int j = 0; j < C; j++)
                dst[j] = __float2bfloat16(__expf(x * other[j] - m) * inv);
        }
    }
}

// ---------------- kernel 3: attention pooling, pipelined multi-tile HMMA ----
// TPB=4, grid (64,4,2) = 512 blocks; pointer-increment loaders; 3 CTAs/SM.
#define PXT   256
#define TPB   4
#define FROW  264    // bf16 elems; 528B row stride
#define SROW  72     // bf16 elems; 144B row stride
#define ATP_SMEM_BYTES (2 * 64 * FROW * 2 + 64 * SROW * 2)

__global__ void __launch_bounds__(256, 3)
atpool_kernel() {
    extern __shared__ char smraw[];
    __nv_bfloat16* sF0 = (__nv_bfloat16*)smraw;            // [64][FROW]
    __nv_bfloat16* sF1 = sF0 + 64 * FROW;                  // [64][FROW]
    __nv_bfloat16* sS  = sF1 + 64 * FROW;                  // [64][SROW]

    int tid = threadIdx.x, warp = tid >> 5, lane = tid & 31;
    int tg = blockIdx.x, b = blockIdx.y, z = blockIdx.z;
    const __nv_bfloat16* fb = &d_fb[z][b][0][0];
    const __nv_bfloat16* Sg = d_Sb[z][b];

    uint32_t sS_base = (uint32_t)__cvta_generic_to_shared(sS);
    uint32_t sFb[2] = { (uint32_t)__cvta_generic_to_shared(sF0),
                        (uint32_t)__cvta_generic_to_shared(sF1) };

    // S tile once (8KB)
    #pragma unroll
    for (int it = 0; it < 2; it++) {
        int idx = tid + it * 256;
        int row = idx >> 3, col = idx & 7;
        cp_async16(sS_base + row * 144 + col * 16, Sg + row * 64 + col * 8);
    }

    // per-thread invariant load addressing: row=(tid>>5)+it*8, col=tid&31
    const __nv_bfloat16* bsrc = fb + (size_t)(tid >> 5) * HW + (tid & 31) * 8;
    uint32_t bdst = (uint32_t)((tid >> 5) * 528 + (tid & 31) * 16);

    {   // F tile 0
        const __nv_bfloat16* s = bsrc + tg * TPB * PXT;
        uint32_t d = sFb[0] + bdst;
        #pragma unroll
        for (int it = 0; it < 8; it++) {
            cp_async16(d, s);
            d += 8 * 528;
            s += (size_t)8 * HW;
        }
    }
    cp_async_commit();

    for (int t = 0; t < TPB; t++) {
        int cur = t & 1;
        if (t + 1 < TPB) {
            const __nv_bfloat16* s = bsrc + (tg * TPB + t + 1) * PXT;
            uint32_t d = sFb[cur ^ 1] + bdst;
            #pragma unroll
            for (int it = 0; it < 8; it++) {
                cp_async16(d, s);
                d += 8 * 528;
                s += (size_t)8 * HW;
            }
            cp_async_commit();
            cp_async_wait<1>();
        } else {
            cp_async_wait<0>();
        }
        __syncthreads();

        int pxw = warp * 32;
        float rm0[4], rm1[4], rs0[4], rs1[4];
        #pragma unroll
        for (int nt = 0; nt < 4; nt++) {
            rm0[nt] = -INFINITY; rm1[nt] = -INFINITY;
            rs0[nt] = 0.f;       rs1[nt] = 0.f;
        }

        #pragma unroll
        for (int mt = 0; mt < 4; mt++) {
            float acc[4][4];
            #pragma unroll
            for (int nt = 0; nt < 4; nt++)
                #pragma unroll
                for (int r = 0; r < 4; r++) acc[nt][r] = 0.f;

            #pragma unroll
            for (int kt = 0; kt < 4; kt++) {
                uint32_t a[4];
                {
                    int row = mt * 16 + (lane & 15);
                    int col = kt * 16 + ((lane & 16) ? 8 : 0);
                    ldsm_x4(a, sS_base + row * 144 + col * 2);
                }
                uint32_t bfr[2][4];
                #pragma unroll
                for (int h = 0; h < 2; h++) {
                    int krow = kt * 16 + (lane & 15);
                    int px   = pxw + h * 16 + ((lane & 16) ? 8 : 0);
                    ldsm_x4_trans(bfr[h], sFb[cur] + krow * 528 + px * 2);
                }
                #pragma unroll
                for (int nt = 0; nt < 4; nt++)
                    mma_bf16(acc[nt], a,
                             bfr[nt >> 1][(nt & 1) * 2 + 0],
                             bfr[nt >> 1][(nt & 1) * 2 + 1]);
            }
            #pragma unroll
            for (int nt = 0; nt < 4; nt++) {
                rm0[nt] = fmaxf(rm0[nt], fmaxf(acc[nt][0], acc[nt][2]));
                rm1[nt] = fmaxf(rm1[nt], fmaxf(acc[nt][1], acc[nt][3]));
                rs0[nt] += acc[nt][0] + acc[nt][2];
                rs1[nt] += acc[nt][1] + acc[nt][3];
            }
        }

        int tpx = (tg * TPB + t) * PXT;
        float* pmax  = &d_pooled[z][b][1][tpx];
        float* pmean = &d_pooled[z][b][0][tpx];
        #pragma unroll
        for (int nt = 0; nt < 4; nt++) {
            float m0 = rm0[nt], m1 = rm1[nt], s0 = rs0[nt], s1 = rs1[nt];
            #pragma unroll
            for (int off = 4; off < 32; off <<= 1) {
                m0 = fmaxf(m0, __shfl_xor_sync(0xffffffffu, m0, off));
                m1 = fmaxf(m1, __shfl_xor_sync(0xffffffffu, m1, off));
                s0 += __shfl_xor_sync(0xffffffffu, s0, off);
                s1 += __shfl_xor_sync(0xffffffffu, s1, off);
            }
            if (lane < 4) {
                int px = pxw + nt * 8 + lane * 2;
                pmax[px]      = m0;
                pmax[px + 1]  = m1;
                pmean[px]     = s0 * (1.f / 64.f);
                pmean[px + 1] = s1 * (1.f / 64.f);
            }
        }
        __syncthreads();
    }
}

// ---------------- kernel 4: fused conv1+conv2 + softmax partials ------------
#define CTX 64
#define CTY 16
__global__ void __launch_bounds__(256)
convf_kernel(const float* __restrict__ cw1, const float* __restrict__ cb1,
             const float* __restrict__ cw2, const float* __restrict__ cb2) {
    __shared__ float in0[20][68];
    __shared__ float in1[20][68];
    __shared__ float t1s[18][66];
    __shared__ float rbuf[256];

    int tid = threadIdx.x;
    int ox = blockIdx.x * CTX;
    int oy = blockIdx.y * CTY;
    int zb = blockIdx.z; int z = zb >> 2, b = zb & 3;
    const float* p0 = d_pooled[z][b][0];
    const float* p1 = d_pooled[z][b][1];

    float w1r[18], w2r[9];
    #pragma unroll
    for (int i = 0; i < 18; i++) w1r[i] = cw1[i];
    #pragma unroll
    for (int i = 0; i < 9;  i++) w2r[i] = cw2[i];
    float bias1 = cb1[0], bias2 = cb2[0];

    for (int idx = tid; idx < 20 * 68; idx += 256) {
        int ly = idx / 68, lx = idx % 68;
        int gy = oy - 2 + ly, gx = ox - 2 + lx;
        bool ok = (gy >= 0) & (gy < 256) & (gx >= 0) & (gx < 256);
        int q = gy * 256 + gx;
        in0[ly][lx] = ok ? p0[q] : 0.f;
        in1[ly][lx] = ok ? p1[q] : 0.f;
    }
    __syncthreads();

    for (int idx = tid; idx < 18 * 66; idx += 256) {
        int ty = idx / 66, tx = idx % 66;
        int gy = oy - 1 + ty, gx = ox - 1 + tx;
        float v = 0.f;
        if ((gy >= 0) & (gy < 256) & (gx >= 0) & (gx < 256)) {
            float acc = bias1;
            #pragma unroll
            for (int dy = 0; dy < 3; dy++)
                #pragma unroll
                for (int dx = 0; dx < 3; dx++) {
                    acc += w1r[dy * 3 + dx]     * in0[ty + dy][tx + dx];
                    acc += w1r[9 + dy * 3 + dx] * in1[ty + dy][tx + dx];
                }
            v = fmaxf(acc, 0.f);
        }
        t1s[ty][tx] = v;
    }
    __syncthreads();

    float vals[4];
    #pragma unroll
    for (int r = 0; r < 4; r++) {
        int idx = tid + r * 256;
        int y = idx >> 6, x = idx & 63;
        float acc = bias2;
        #pragma unroll
        for (int dy = 0; dy < 3; dy++)
            #pragma unroll
            for (int dx = 0; dx < 3; dx++)
                acc += w2r[dy * 3 + dx] * t1s[y + dy][x + dx];
        vals[r] = acc;
        d_t2[z][b][(oy + y) * 256 + (ox + x)] = acc;
    }

    float lm = fmaxf(fmaxf(vals[0], vals[1]), fmaxf(vals[2], vals[3]));
    rbuf[tid] = lm;
    __syncthreads();
    for (int o = 128; o > 0; o >>= 1) {
        if (tid < o) rbuf[tid] = fmaxf(rbuf[tid], rbuf[tid + o]);
        __syncthreads();
    }
    float Mblk = rbuf[0];
    __syncthreads();
    float ls = __expf(vals[0] - Mblk) + __expf(vals[1] - Mblk)
             + __expf(vals[2] - Mblk) + __expf(vals[3] - Mblk);
    rbuf[tid] = ls;
    __syncthreads();
    for (int o = 128; o > 0; o >>= 1) {
        if (tid < o) rbuf[tid] += rbuf[tid + o];
        __syncthreads();
    }
    if (tid == 0) {
        int blk = blockIdx.y * 4 + blockIdx.x;   // 0..63
        d_cmax[zb][blk] = Mblk;
        d_csum[zb][blk] = rbuf[0];
    }
}

// ---------------- kernel 5: gate = softmax(t2) over HW ----------------------
__global__ void gate_kernel() {
    __shared__ float sM, sS2;
    int tid = threadIdx.x;
    int zb = blockIdx.y; int z = zb >> 2, b = zb & 3;

    if (tid < 32) {
        float m0 = d_cmax[zb][tid], m1 = d_cmax[zb][tid + 32];
        float mm = fmaxf(m0, m1);
        #pragma unroll
        for (int off = 16; off > 0; off >>= 1)
            mm = fmaxf(mm, __shfl_xor_sync(0xffffffffu, mm, off));
        float s = d_csum[zb][tid]      * __expf(m0 - mm)
                + d_csum[zb][tid + 32] * __expf(m1 - mm);
        #pragma unroll
        for (int off = 16; off > 0; off >>= 1)
            s += __shfl_xor_sync(0xffffffffu, s, off);
        if (tid == 0) { sM = mm; sS2 = s; }
    }
    __syncthreads();
    float M = sM, rinv = 1.f / sS2;

    int i4 = blockIdx.x * 256 + tid;
    float4 yv = *(const float4*)(&d_t2[z][b][i4 * 4]);
    float4 g;
    g.x = __expf(yv.x - M) * rinv;
    g.y = __expf(yv.y - M) * rinv;
    g.z = __expf(yv.z - M) * rinv;
    g.w = __expf(yv.w - M) * rinv;
    *(float4*)(&d_g[z][b][i4 * 4]) = g;
}

// ---------------- kernel 6: o = f*(1+g), 2 float4 per thread ----------------
__global__ void out_kernel(const float* __restrict__ f1,
                           const float* __restrict__ f2,
                           float* __restrict__ out) {
    unsigned idx  = blockIdx.x * 256u + threadIdx.x;
    unsigned pr   = idx & 8191u;
    unsigned c    = (idx >> 13) & 63u;
    unsigned b    = (idx >> 19) & 3u;
    unsigned z    = 1u - (idx >> 21);
    const float* f = z ? f2 : f1;

    const float4* gp = (const float4*)&d_g[z][b][pr * 8];
    float4 g0 = gp[0], g1 = gp[1];
    size_t base = ((size_t)(b * 64u + c)) * HW + pr * 8u;
    const float4* fp = (const float4*)(f + base);
    float4 v0 = fp[0], v1 = fp[1];
    float4 o0, o1;
    o0.x = fmaf(v0.x, g0.x, v0.x); o0.y = fmaf(v0.y, g0.y, v0.y);
    o0.z = fmaf(v0.z, g0.z, v0.z); o0.w = fmaf(v0.w, g0.w, v0.w);
    o1.x = fmaf(v1.x, g1.x, v1.x); o1.y = fmaf(v1.y, g1.y, v1.y);
    o1.z = fmaf(v1.z, g1.z, v1.z); o1.w = fmaf(v1.w, g1.w, v1.w);
    float4* op = (float4*)(out + (size_t)z * ((size_t)B * C * HW) + base);
    op[0] = o0; op[1] = o1;
}

// ---------------- launch ------------------------------------------------------
extern "C" void kernel_launch(void* const* d_in, const int* in_sizes, int n_in,
                              void* d_out, int out_size) {
    const float* f1 = (const float*)d_in[0];
    const float* f2 = (const float*)d_in[1];

    cudaFuncSetAttribute(atpool_kernel,
                         cudaFuncAttributeMaxDynamicSharedMemorySize,
                         ATP_SMEM_BYTES);

    stats_kernel<<<2048, 256>>>(f1, f2);

    mlp_kernel<<<1, 256>>>(
        (const float*)d_in[2],  (const float*)d_in[3],
        (const float*)d_in[4],  (const float*)d_in[5],
        (const float*)d_in[6],  (const float*)d_in[7],
        (const float*)d_in[8],  (const float*)d_in[9],
        (const float*)d_in[10], (const float*)d_in[11],
        (const float*)d_in[12], (const float*)d_in[13],
        (const float*)d_in[14], (const float*)d_in[15],
        (const float*)d_in[16], (const float*)d_in[17]);

    atpool_kernel<<<dim3(64, 4, 2), 256, ATP_SMEM_BYTES>>>();

    convf_kernel<<<dim3(4, 16, 8), 256>>>(
        (const float*)d_in[18], (const float*)d_in[19],
        (const float*)d_in[20], (const float*)d_in[21]);

    gate_kernel<<<dim3(64, 8), 256>>>();

    out_kernel<<<16384, 256>>>(f1, f2, (float*)d_out);
}

// round 12
// speedup vs baseline: 1.2080x; 1.1135x over previous
#include <cuda_runtime.h>
#include <cuda_bf16.h>
#include <math.h>
#include <stdint.h>

#define B  4
#define C  64
#define CR 32
#define HW 65536

// ---------------- scratch (device globals) ----------------------------------
__device__ float d_ps[512][4];                // stats partial sums
__device__ float d_pm[512][4];                // stats partial maxes
__device__ __nv_bfloat16 d_fb[2][B][C][HW];   // bf16 copy of f (written by stats)
__device__ __nv_bfloat16 d_Sb[2][B][C*C];     // softmaxed S, bf16
__device__ float d_pooled[2][B][2][HW];
__device__ float d_g [2][B][HW];              // u = exp(t2 - Mblk) per pixel
__device__ float d_cmax[8][64];               // per conv-block max
__device__ float d_csum[8][64];               // per conv-block sum of u
__device__ float d_factor[8][64];             // exp(Mblk-M)/S per conv-block

// ---------------- PTX helpers ------------------------------------------------
__device__ __forceinline__ uint32_t pack_bf16(float lo, float hi) {
    uint32_t d;
    asm("cvt.rn.bf16x2.f32 %0, %1, %2;" : "=r"(d) : "f"(hi), "f"(lo));
    return d;
}
__device__ __forceinline__ void ldsm_x4(uint32_t r[4], uint32_t addr) {
    asm volatile("ldmatrix.sync.aligned.m8n8.x4.shared.b16 {%0,%1,%2,%3}, [%4];"
                 : "=r"(r[0]), "=r"(r[1]), "=r"(r[2]), "=r"(r[3]) : "r"(addr));
}
__device__ __forceinline__ void ldsm_x4_trans(uint32_t r[4], uint32_t addr) {
    asm volatile("ldmatrix.sync.aligned.m8n8.x4.trans.shared.b16 {%0,%1,%2,%3}, [%4];"
                 : "=r"(r[0]), "=r"(r[1]), "=r"(r[2]), "=r"(r[3]) : "r"(addr));
}
__device__ __forceinline__ void mma_bf16(float d[4], const uint32_t a[4],
                                         uint32_t b0, uint32_t b1) {
    asm volatile(
        "mma.sync.aligned.m16n8k16.row.col.f32.bf16.bf16.f32 "
        "{%0,%1,%2,%3}, {%4,%5,%6,%7}, {%8,%9}, {%0,%1,%2,%3};"
        : "+f"(d[0]), "+f"(d[1]), "+f"(d[2]), "+f"(d[3])
        : "r"(a[0]), "r"(a[1]), "r"(a[2]), "r"(a[3]), "r"(b0), "r"(b1));
}
__device__ __forceinline__ void cp_async16(uint32_t dst, const void* src) {
    asm volatile("cp.async.cg.shared.global [%0], [%1], 16;"
                 :: "r"(dst), "l"(src));
}
__device__ __forceinline__ void cp_async_commit() {
    asm volatile("cp.async.commit_group;");
}
template <int N>
__device__ __forceinline__ void cp_async_wait() {
    asm volatile("cp.async.wait_group %0;" :: "n"(N) : "memory");
}

// ---------------- kernel 1: stats partials + bf16 conversion ----------------
__global__ void stats_kernel(const float* __restrict__ f1,
                             const float* __restrict__ f2) {
    int lin   = blockIdx.x;              // 0..2047
    int row   = 511 - (lin >> 2);        // f2 chunks first
    int chunk = lin & 3;
    int z = (row >= 256);
    int idx = row & 255;
    const float* f = (z ? f2 : f1) + (size_t)idx * HW;
    __nv_bfloat16* fbo = &d_fb[z][idx >> 6][idx & 63][chunk * 16384];
    int tid = threadIdx.x, warp = tid >> 5, lane = tid & 31;
    const float4* f4 = (const float4*)f + chunk * 4096;

    float s = 0.f, m = -INFINITY;
    #pragma unroll
    for (int k = 0; k < 16; k++) {
        int i = tid + k * 256;
        float4 v = f4[i];
        s += (v.x + v.y) + (v.z + v.w);
        m = fmaxf(m, fmaxf(fmaxf(v.x, v.y), fmaxf(v.z, v.w)));
        uint32_t u0 = pack_bf16(v.x, v.y);
        uint32_t u1 = pack_bf16(v.z, v.w);
        *(uint2*)(fbo + i * 4) = make_uint2(u0, u1);
    }
    #pragma unroll
    for (int off = 16; off > 0; off >>= 1) {
        s += __shfl_xor_sync(0xffffffffu, s, off);
        m = fmaxf(m, __shfl_xor_sync(0xffffffffu, m, off));
    }
    __shared__ float ws[8], wm[8];
    if (lane == 0) { ws[warp] = s; wm[warp] = m; }
    __syncthreads();
    if (tid == 0) {
        float S = ws[0], M = wm[0];
        #pragma unroll
        for (int w = 1; w < 8; w++) { S += ws[w]; M = fmaxf(M, wm[w]); }
        d_ps[row][chunk] = S; d_pm[row][chunk] = M;
    }
}

// ---------------- kernel 2: reduce partials + MLPs + cross softmax -> bf16 --
__global__ void mlp_kernel(
    const float* __restrict__ w_a1,  const float* __restrict__ b_a1,
    const float* __restrict__ w_m1,  const float* __restrict__ b_m1,
    const float* __restrict__ w_a11, const float* __restrict__ b_a11,
    const float* __restrict__ w_m11, const float* __restrict__ b_m11,
    const float* __restrict__ w_a2,  const float* __restrict__ b_a2,
    const float* __restrict__ w_m2,  const float* __restrict__ b_m2,
    const float* __restrict__ w_a22, const float* __restrict__ b_a22,
    const float* __restrict__ w_m22, const float* __restrict__ b_m22)
{
    __shared__ float s_stat[4][B][C];
    __shared__ float s_hid [4][B][CR];
    __shared__ float s_a   [2][B][C];
    __shared__ __nv_bfloat16 s_Sb[B][C * C];   // 32 KB staging per zz
    int tid = threadIdx.x;

    {
        int b = tid >> 6, c = tid & 63;
        float s0 = d_ps[tid][0] + d_ps[tid][1] + d_ps[tid][2] + d_ps[tid][3];
        float m0 = fmaxf(fmaxf(d_pm[tid][0], d_pm[tid][1]),
                         fmaxf(d_pm[tid][2], d_pm[tid][3]));
        int r1 = tid + 256;
        float s1 = d_ps[r1][0] + d_ps[r1][1] + d_ps[r1][2] + d_ps[r1][3];
        float m1 = fmaxf(fmaxf(d_pm[r1][0], d_pm[r1][1]),
                         fmaxf(d_pm[r1][2], d_pm[r1][3]));
        s_stat[0][b][c] = s0 * (1.f / HW);
        s_stat[1][b][c] = m0;
        s_stat[2][b][c] = s1 * (1.f / HW);
        s_stat[3][b][c] = m1;
    }
    __syncthreads();

    const float* Wp[4] = {w_a1, w_m1, w_a2, w_m2};
    const float* Bp[4] = {b_a1, b_m1, b_a2, b_m2};
    for (int e = tid; e < 4 * B * CR; e += 256) {
        int p = e >> 7, b = (e >> 5) & 3, k = e & 31;
        const float* wr = Wp[p] + k * C;
        float acc = Bp[p][k];
        #pragma unroll 8
        for (int c2 = 0; c2 < C; c2++) acc += s_stat[p][b][c2] * wr[c2];
        s_hid[p][b][k] = fmaxf(acc, 0.f);
    }
    __syncthreads();

    {
        int b = tid >> 6, i = tid & 63;
        float a1 = b_a11[i] + b_m11[i];
        float a2 = b_a22[i] + b_m22[i];
        #pragma unroll 8
        for (int k = 0; k < CR; k++) {
            a1 += s_hid[0][b][k] * w_a11[i * CR + k] + s_hid[1][b][k] * w_m11[i * CR + k];
            a2 += s_hid[2][b][k] * w_a22[i * CR + k] + s_hid[3][b][k] * w_m22[i * CR + k];
        }
        s_a[0][b][i] = a1;
        s_a[1][b][i] = a2;
    }
    __syncthreads();

    // softmax rows -> bf16, staged in smem then coalesced copy
    for (int zz = 0; zz < 2; zz++) {
        int b = tid >> 6, i = tid & 63;
        float x = s_a[zz][b][i];
        const float* other = s_a[1 - zz][b];
        float m = -INFINITY;
        #pragma unroll 8
        for (int j = 0; j < C; j++) m = fmaxf(m, x * other[j]);
        float Z = 0.f;
        #pragma unroll 8
        for (int j = 0; j < C; j++) Z += __expf(x * other[j] - m);
        float inv = 1.f / Z;
        __nv_bfloat16* dst = &s_Sb[b][i * C];
        #pragma unroll 8
        for (int j = 0; j < C; j++)
            dst[j] = __float2bfloat16(__expf(x * other[j] - m) * inv);
        __syncthreads();
        const uint4* src4 = (const uint4*)&s_Sb[0][0];
        uint4* dst4 = (uint4*)&d_Sb[zz][0][0];
        #pragma unroll
        for (int k = tid; k < (B * C * C * 2) / 16; k += 256)
            dst4[k] = src4[k];
        __syncthreads();
    }
}

// ---------------- kernel 3: attention pooling, pipelined multi-tile HMMA ----
#define PXT   256
#define TPB   4
#define FROW  264    // bf16 elems; 528B row stride
#define SROW  72     // bf16 elems; 144B row stride
#define ATP_SMEM_BYTES (2 * 64 * FROW * 2 + 64 * SROW * 2)

__global__ void __launch_bounds__(256, 3)
atpool_kernel() {
    extern __shared__ char smraw[];
    __nv_bfloat16* sF0 = (__nv_bfloat16*)smraw;            // [64][FROW]
    __nv_bfloat16* sF1 = sF0 + 64 * FROW;                  // [64][FROW]
    __nv_bfloat16* sS  = sF1 + 64 * FROW;                  // [64][SROW]

    int tid = threadIdx.x, warp = tid >> 5, lane = tid & 31;
    int tg = blockIdx.x, b = blockIdx.y, z = blockIdx.z;
    const __nv_bfloat16* fb = &d_fb[z][b][0][0];
    const __nv_bfloat16* Sg = d_Sb[z][b];

    uint32_t sS_base = (uint32_t)__cvta_generic_to_shared(sS);
    uint32_t sFb[2] = { (uint32_t)__cvta_generic_to_shared(sF0),
                        (uint32_t)__cvta_generic_to_shared(sF1) };

    #pragma unroll
    for (int it = 0; it < 2; it++) {
        int idx = tid + it * 256;
        int row = idx >> 3, col = idx & 7;
        cp_async16(sS_base + row * 144 + col * 16, Sg + row * 64 + col * 8);
    }

    const __nv_bfloat16* bsrc = fb + (size_t)(tid >> 5) * HW + (tid & 31) * 8;
    uint32_t bdst = (uint32_t)((tid >> 5) * 528 + (tid & 31) * 16);

    {
        const __nv_bfloat16* s = bsrc + tg * TPB * PXT;
        uint32_t d = sFb[0] + bdst;
        #pragma unroll
        for (int it = 0; it < 8; it++) {
            cp_async16(d, s);
            d += 8 * 528;
            s += (size_t)8 * HW;
        }
    }
    cp_async_commit();

    for (int t = 0; t < TPB; t++) {
        int cur = t & 1;
        if (t + 1 < TPB) {
            const __nv_bfloat16* s = bsrc + (tg * TPB + t + 1) * PXT;
            uint32_t d = sFb[cur ^ 1] + bdst;
            #pragma unroll
            for (int it = 0; it < 8; it++) {
                cp_async16(d, s);
                d += 8 * 528;
                s += (size_t)8 * HW;
            }
            cp_async_commit();
            cp_async_wait<1>();
        } else {
            cp_async_wait<0>();
        }
        __syncthreads();

        int pxw = warp * 32;
        float rm0[4], rm1[4], rs0[4], rs1[4];
        #pragma unroll
        for (int nt = 0; nt < 4; nt++) {
            rm0[nt] = -INFINITY; rm1[nt] = -INFINITY;
            rs0[nt] = 0.f;       rs1[nt] = 0.f;
        }

        #pragma unroll
        for (int mt = 0; mt < 4; mt++) {
            float acc[4][4];
            #pragma unroll
            for (int nt = 0; nt < 4; nt++)
                #pragma unroll
                for (int r = 0; r < 4; r++) acc[nt][r] = 0.f;

            #pragma unroll
            for (int kt = 0; kt < 4; kt++) {
                uint32_t a[4];
                {
                    int row = mt * 16 + (lane & 15);
                    int col = kt * 16 + ((lane & 16) ? 8 : 0);
                    ldsm_x4(a, sS_base + row * 144 + col * 2);
                }
                uint32_t bfr[2][4];
                #pragma unroll
                for (int h = 0; h < 2; h++) {
                    int krow = kt * 16 + (lane & 15);
                    int px   = pxw + h * 16 + ((lane & 16) ? 8 : 0);
                    ldsm_x4_trans(bfr[h], sFb[cur] + krow * 528 + px * 2);
                }
                #pragma unroll
                for (int nt = 0; nt < 4; nt++)
                    mma_bf16(acc[nt], a,
                             bfr[nt >> 1][(nt & 1) * 2 + 0],
                             bfr[nt >> 1][(nt & 1) * 2 + 1]);
            }
            #pragma unroll
            for (int nt = 0; nt < 4; nt++) {
                rm0[nt] = fmaxf(rm0[nt], fmaxf(acc[nt][0], acc[nt][2]));
                rm1[nt] = fmaxf(rm1[nt], fmaxf(acc[nt][1], acc[nt][3]));
                rs0[nt] += acc[nt][0] + acc[nt][2];
                rs1[nt] += acc[nt][1] + acc[nt][3];
            }
        }

        int tpx = (tg * TPB + t) * PXT;
        float* pmax  = &d_pooled[z][b][1][tpx];
        float* pmean = &d_pooled[z][b][0][tpx];
        #pragma unroll
        for (int nt = 0; nt < 4; nt++) {
            float m0 = rm0[nt], m1 = rm1[nt], s0 = rs0[nt], s1 = rs1[nt];
            #pragma unroll
            for (int off = 4; off < 32; off <<= 1) {
                m0 = fmaxf(m0, __shfl_xor_sync(0xffffffffu, m0, off));
                m1 = fmaxf(m1, __shfl_xor_sync(0xffffffffu, m1, off));
                s0 += __shfl_xor_sync(0xffffffffu, s0, off);
                s1 += __shfl_xor_sync(0xffffffffu, s1, off);
            }
            if (lane < 4) {
                int px = pxw + nt * 8 + lane * 2;
                pmax[px]      = m0;
                pmax[px + 1]  = m1;
                pmean[px]     = s0 * (1.f / 64.f);
                pmean[px + 1] = s1 * (1.f / 64.f);
            }
        }
        __syncthreads();
    }
}

// ---------------- kernel 4: fused conv1+conv2, emits u=exp(t2-Mblk) ---------
#define CTX 64
#define CTY 16
__global__ void __launch_bounds__(256)
convf_kernel(const float* __restrict__ cw1, const float* __restrict__ cb1,
             const float* __restrict__ cw2, const float* __restrict__ cb2) {
    __shared__ float in0[20][68];
    __shared__ float in1[20][68];
    __shared__ float t1s[18][66];
    __shared__ float wred[8], wsum[8];

    int tid = threadIdx.x, warp = tid >> 5, lane = tid & 31;
    int ox = blockIdx.x * CTX;
    int oy = blockIdx.y * CTY;
    int zb = blockIdx.z; int z = zb >> 2, b = zb & 3;
    const float* p0 = d_pooled[z][b][0];
    const float* p1 = d_pooled[z][b][1];

    float w1r[18], w2r[9];
    #pragma unroll
    for (int i = 0; i < 18; i++) w1r[i] = cw1[i];
    #pragma unroll
    for (int i = 0; i < 9;  i++) w2r[i] = cw2[i];
    float bias1 = cb1[0], bias2 = cb2[0];

    for (int idx = tid; idx < 20 * 68; idx += 256) {
        int ly = idx / 68, lx = idx % 68;
        int gy = oy - 2 + ly, gx = ox - 2 + lx;
        bool ok = (gy >= 0) & (gy < 256) & (gx >= 0) & (gx < 256);
        int q = gy * 256 + gx;
        in0[ly][lx] = ok ? p0[q] : 0.f;
        in1[ly][lx] = ok ? p1[q] : 0.f;
    }
    __syncthreads();

    for (int idx = tid; idx < 18 * 66; idx += 256) {
        int ty = idx / 66, tx = idx % 66;
        int gy = oy - 1 + ty, gx = ox - 1 + tx;
        float v = 0.f;
        if ((gy >= 0) & (gy < 256) & (gx >= 0) & (gx < 256)) {
            float acc = bias1;
            #pragma unroll
            for (int dy = 0; dy < 3; dy++)
                #pragma unroll
                for (int dx = 0; dx < 3; dx++) {
                    acc += w1r[dy * 3 + dx]     * in0[ty + dy][tx + dx];
                    acc += w1r[9 + dy * 3 + dx] * in1[ty + dy][tx + dx];
                }
            v = fmaxf(acc, 0.f);
        }
        t1s[ty][tx] = v;
    }
    __syncthreads();

    float vals[4];
    #pragma unroll
    for (int r = 0; r < 4; r++) {
        int idx = tid + r * 256;
        int y = idx >> 6, x = idx & 63;
        float acc = bias2;
        #pragma unroll
        for (int dy = 0; dy < 3; dy++)
            #pragma unroll
            for (int dx = 0; dx < 3; dx++)
                acc += w2r[dy * 3 + dx] * t1s[y + dy][x + dx];
        vals[r] = acc;
    }

    // block max via warp shuffles (2 barriers total)
    float lm = fmaxf(fmaxf(vals[0], vals[1]), fmaxf(vals[2], vals[3]));
    #pragma unroll
    for (int off = 16; off > 0; off >>= 1)
        lm = fmaxf(lm, __shfl_xor_sync(0xffffffffu, lm, off));
    if (lane == 0) wred[warp] = lm;
    __syncthreads();
    float Mblk = wred[0];
    #pragma unroll
    for (int w = 1; w < 8; w++) Mblk = fmaxf(Mblk, wred[w]);

    // write u and accumulate sum
    float ls = 0.f;
    #pragma unroll
    for (int r = 0; r < 4; r++) {
        int idx = tid + r * 256;
        int y = idx >> 6, x = idx & 63;
        float u = __expf(vals[r] - Mblk);
        ls += u;
        d_g[z][b][(oy + y) * 256 + (ox + x)] = u;
    }
    #pragma unroll
    for (int off = 16; off > 0; off >>= 1)
        ls += __shfl_xor_sync(0xffffffffu, ls, off);
    if (lane == 0) wsum[warp] = ls;
    __syncthreads();
    if (tid == 0) {
        float S = wsum[0];
        #pragma unroll
        for (int w = 1; w < 8; w++) S += wsum[w];
        int blk = blockIdx.y * 4 + blockIdx.x;   // 0..63
        d_cmax[zb][blk] = Mblk;
        d_csum[zb][blk] = S;
    }
}

// ---------------- kernel 5: per-(z,b) factor = exp(Mblk-M)/S ----------------
__global__ void factor_kernel() {
    int tid = threadIdx.x, warp = tid >> 5, lane = tid & 31;  // warp = zb
    float m0 = d_cmax[warp][lane], m1 = d_cmax[warp][lane + 32];
    float mm = fmaxf(m0, m1);
    #pragma unroll
    for (int off = 16; off > 0; off >>= 1)
        mm = fmaxf(mm, __shfl_xor_sync(0xffffffffu, mm, off));
    float s = d_csum[warp][lane]      * __expf(m0 - mm)
            + d_csum[warp][lane + 32] * __expf(m1 - mm);
    #pragma unroll
    for (int off = 16; off > 0; off >>= 1)
        s += __shfl_xor_sync(0xffffffffu, s, off);
    float rinv = 1.f / s;
    d_factor[warp][lane]      = __expf(m0 - mm) * rinv;
    d_factor[warp][lane + 32] = __expf(m1 - mm) * rinv;
}

// ---------------- kernel 6: o = f*(1+g), g = u*factor, streaming stores -----
__global__ void out_kernel(const float* __restrict__ f1,
                           const float* __restrict__ f2,
                           float* __restrict__ out) {
    unsigned idx  = blockIdx.x * 256u + threadIdx.x;
    unsigned pr   = idx & 8191u;
    unsigned c    = (idx >> 13) & 63u;
    unsigned b    = (idx >> 19) & 3u;
    unsigned z    = 1u - (idx >> 21);
    const float* f = z ? f2 : f1;

    unsigned pix0 = pr * 8u;
    unsigned fidx = ((pix0 >> 12) << 2) | ((pix0 >> 6) & 3u);
    float fac = d_factor[(z << 2) | b][fidx];

    const float4* gp = (const float4*)&d_g[z][b][pix0];
    float4 g0 = gp[0], g1 = gp[1];
    size_t base = ((size_t)(b * 64u + c)) * HW + pix0;
    const float4* fp = (const float4*)(f + base);
    float4 v0 = fp[0], v1 = fp[1];
    float4 o0, o1;
    o0.x = fmaf(v0.x, g0.x * fac, v0.x); o0.y = fmaf(v0.y, g0.y * fac, v0.y);
    o0.z = fmaf(v0.z, g0.z * fac, v0.z); o0.w = fmaf(v0.w, g0.w * fac, v0.w);
    o1.x = fmaf(v1.x, g1.x * fac, v1.x); o1.y = fmaf(v1.y, g1.y * fac, v1.y);
    o1.z = fmaf(v1.z, g1.z * fac, v1.z); o1.w = fmaf(v1.w, g1.w * fac, v1.w);
    float4* op = (float4*)(out + (size_t)z * ((size_t)B * C * HW) + base);
    __stcs(&op[0], o0);
    __stcs(&op[1], o1);
}

// ---------------- launch ------------------------------------------------------
extern "C" void kernel_launch(void* const* d_in, const int* in_sizes, int n_in,
                              void* d_out, int out_size) {
    const float* f1 = (const float*)d_in[0];
    const float* f2 = (const float*)d_in[1];

    cudaFuncSetAttribute(atpool_kernel,
                         cudaFuncAttributeMaxDynamicSharedMemorySize,
                         ATP_SMEM_BYTES);

    stats_kernel<<<2048, 256>>>(f1, f2);

    mlp_kernel<<<1, 256>>>(
        (const float*)d_in[2],  (const float*)d_in[3],
        (const float*)d_in[4],  (const float*)d_in[5],
        (const float*)d_in[6],  (const float*)d_in[7],
        (const float*)d_in[8],  (const float*)d_in[9],
        (const float*)d_in[10], (const float*)d_in[11],
        (const float*)d_in[12], (const float*)d_in[13],
        (const float*)d_in[14], (const float*)d_in[15],
        (const float*)d_in[16], (const float*)d_in[17]);

    atpool_kernel<<<dim3(64, 4, 2), 256, ATP_SMEM_BYTES>>>();

    convf_kernel<<<dim3(4, 16, 8), 256>>>(
        (const float*)d_in[18], (const float*)d_in[19],
        (const float*)d_in[20], (const float*)d_in[21]);

    factor_kernel<<<1, 256>>>();

    out_kernel<<<16384, 256>>>(f1, f2, (float*)d_out);
}